// round 10
// baseline (speedup 1.0000x reference)
#include <cuda_runtime.h>
#include <cuda_fp16.h>
#include <math.h>
#include <stdint.h>

#define BB 8
#define SS 2048
#define DD 512
#define MTOT (BB*SS)

__device__ __half g_xh[MTOT*DD];
__device__ __half g_Wth[3][DD*DD], g_Wtl[3][DD*DD];
__device__ __half g_Qh[MTOT*DD];
__device__ __half g_Kh[MTOT*DD];
__device__ float  g_Vf[MTOT*DD];
__device__ __half g_Vth[MTOT*DD];
__device__ __half g_Sc[(long long)BB*SS*SS];
__device__ float  g_rowm[MTOT], g_rowinv[MTOT];

__device__ __forceinline__ uint32_t smem_u32(const void* p){
    uint32_t a;
    asm("{ .reg .u64 t; cvta.to.shared.u64 t, %1; cvt.u32.u64 %0, t; }" : "=r"(a) : "l"(p));
    return a;
}
__device__ __forceinline__ void cpa16(uint32_t dst, const void* src){
    asm volatile("cp.async.cg.shared.global [%0], [%1], 16;" :: "r"(dst), "l"(src));
}
__device__ __forceinline__ void cpa_commit(){ asm volatile("cp.async.commit_group;"); }
template<int N> __device__ __forceinline__ void cpa_wait(){
    asm volatile("cp.async.wait_group %0;" :: "n"(N));
}
__device__ __forceinline__ void ldm_x4(uint32_t* r, uint32_t addr){
    asm volatile("ldmatrix.sync.aligned.m8n8.x4.shared.b16 {%0,%1,%2,%3}, [%4];"
        : "=r"(r[0]), "=r"(r[1]), "=r"(r[2]), "=r"(r[3]) : "r"(addr));
}
__device__ __forceinline__ void mma16816(float* d, const uint32_t* a, uint32_t b0, uint32_t b1){
    asm volatile("mma.sync.aligned.m16n8k16.row.col.f32.f16.f16.f32 "
        "{%0,%1,%2,%3},{%4,%5,%6,%7},{%8,%9},{%0,%1,%2,%3};"
        : "+f"(d[0]), "+f"(d[1]), "+f"(d[2]), "+f"(d[3])
        : "r"(a[0]), "r"(a[1]), "r"(a[2]), "r"(a[3]), "r"(b0), "r"(b1));
}
__device__ __forceinline__ float ex2(float x){
    float r;
    asm("ex2.approx.ftz.f32 %0, %1;" : "=f"(r) : "f"(x));
    return r;
}
#define L2E 1.44269504f

#define PITCH   80
#define MATB    (128*PITCH)

// 128 threads, 4 warps of 64x64, CTA tile 128x128, 2-stage cp.async, single sync.
template<int BSPLIT, int EPI>
__global__ void __launch_bounds__(128, 2)
gemm_mma(const __half* __restrict__ Ah,
         const __half* __restrict__ Bh, const __half* __restrict__ Bl,
         const float* __restrict__ bias,
         float* __restrict__ Cf, __half* __restrict__ Ch,
         int N, int K, float alpha,
         long long sA, long long sB, long long sC)
{
    constexpr int NMAT = 2 + BSPLIT;
    constexpr uint32_t STAGEB = NMAT * MATB;

    extern __shared__ char smem[];
    const uint32_t sb = smem_u32(smem);
    const int tid = threadIdx.x;
    const int wid = tid >> 5, lane = tid & 31;
    const int wr = wid >> 1, wc = wid & 1;
    const int wm0 = wr * 64, wn0 = wc * 64;

    const int row0 = blockIdx.y << 7, col0 = blockIdx.x << 7;
    const long long zA = (long long)blockIdx.z * sA;
    const long long zB = (long long)blockIdx.z * sB;
    const long long zC = (long long)blockIdx.z * sC;

    const __half* gsrc[NMAT];
    gsrc[0] = Ah + zA + (long long)row0 * K;
    gsrc[1] = Bh + zB + (long long)col0 * K;
    if (BSPLIT) gsrc[2] = Bl + zB + (long long)col0 * K;

    const int lrow0 = tid >> 2;
    const int lu    = tid & 3;

    float acc[4][8][4];
#pragma unroll
    for (int i = 0; i < 4; i++)
#pragma unroll
        for (int j = 0; j < 8; j++)
#pragma unroll
            for (int q = 0; q < 4; q++) acc[i][j][q] = 0.0f;

    const int NC = K >> 5;

    auto load_chunk = [&](int stage, int kc) {
        const uint32_t sdst = sb + stage * STAGEB;
#pragma unroll
        for (int m = 0; m < NMAT; m++) {
            const __half* g = gsrc[m] + kc * 32;
#pragma unroll
            for (int it = 0; it < 4; it++) {
                const int row = lrow0 + it * 32;
                cpa16(sdst + m * MATB + row * PITCH + lu * 16,
                      g + (long long)row * K + lu * 8);
            }
        }
    };

    load_chunk(0, 0);
    cpa_commit();

    for (int kc = 0; kc < NC; kc++) {
        const int s = kc & 1;
        cpa_wait<0>();
        __syncthreads();

        const uint32_t sAh = sb + s * STAGEB;
        const uint32_t sBh = sAh + MATB;
        const uint32_t sBl = sAh + 2 * MATB;
        const int lr = lane & 15;
        const int lc = (lane >> 4) * 16;

#pragma unroll
        for (int k16 = 0; k16 < 2; k16++) {
            const uint32_t kb = k16 * 32 + lc;
            uint32_t ah[4][4], bh[4][4], bl[4][4];
#pragma unroll
            for (int i = 0; i < 4; i++)
                ldm_x4(ah[i], sAh + (uint32_t)(wm0 + i * 16 + lr) * PITCH + kb);
#pragma unroll
            for (int jj = 0; jj < 4; jj++) {
                ldm_x4(bh[jj], sBh + (uint32_t)(wn0 + jj * 16 + lr) * PITCH + kb);
                if (BSPLIT) ldm_x4(bl[jj], sBl + (uint32_t)(wn0 + jj * 16 + lr) * PITCH + kb);
            }
            if (k16 == 0 && kc + 1 < NC) {
                load_chunk(s ^ 1, kc + 1);
                cpa_commit();
            }
#pragma unroll
            for (int i = 0; i < 4; i++) {
#pragma unroll
                for (int j = 0; j < 8; j++) {
                    const int jj = j >> 1, sel = j & 1;
                    mma16816(acc[i][j], ah[i], bh[jj][sel], bh[jj][sel + 2]);
                    if (BSPLIT)
                        mma16816(acc[i][j], ah[i], bl[jj][sel], bl[jj][sel + 2]);
                }
            }
        }
    }

    const int er = lane >> 2;
    const int ec = (lane & 3) * 2;
#pragma unroll
    for (int i = 0; i < 4; i++) {
#pragma unroll
        for (int j = 0; j < 8; j++) {
            const int col = col0 + wn0 + j * 8 + ec;
#pragma unroll
            for (int half_m = 0; half_m < 2; half_m++) {
                const int row = row0 + wm0 + i * 16 + er + half_m * 8;
                const float d0 = acc[i][j][half_m * 2 + 0];
                const float d1 = acc[i][j][half_m * 2 + 1];
                if (EPI == 0) {
                    float2 v;
                    v.x = d0 * alpha; v.y = d1 * alpha;
                    if (bias) { v.x += bias[col]; v.y += bias[col + 1]; }
                    *(float2*)(Cf + zC + (long long)row * N + col) = v;
                } else if (EPI == 2) {
                    float f0 = d0 + bias[col];
                    float f1 = d1 + bias[col + 1];
                    *(__half2*)(Ch + zC + (long long)row * N + col) =
                        __halves2half2(__float2half_rn(f0), __float2half_rn(f1));
                } else {
                    *(__half2*)(Ch + zC + (long long)row * N + col) =
                        __halves2half2(__float2half_rn(d0 * alpha), __float2half_rn(d1 * alpha));
                }
            }
        }
    }
}

#define PV_STAGEB (2*MATB)
__global__ void __launch_bounds__(128, 2)
gemm_pv(const __half* __restrict__ Sc, const float* __restrict__ rowm,
        const float* __restrict__ rowinv, const __half* __restrict__ Vt,
        float* __restrict__ out)
{
    extern __shared__ char smem[];
    const uint32_t sb = smem_u32(smem);
    const int tid = threadIdx.x;
    const int wid = tid >> 5, lane = tid & 31;
    const int wr = wid >> 1, wc = wid & 1;
    const int wm0 = wr * 64, wn0 = wc * 64;

    const int col0 = blockIdx.x << 7, row0 = blockIdx.y << 7, b = blockIdx.z;
    const __half* A  = Sc + ((long long)(b * SS + row0)) * SS;
    const __half* Bv = Vt + ((long long)(b * DD + col0)) * SS;
    float* C = out + ((long long)(b * SS + row0)) * DD;

    const int arow = tid;
    const float tm = rowm[b * SS + row0 + arow] * L2E;

    const int brow0 = tid >> 2, bu = tid & 3;

    uint4 areg[4];
    {
        const __half* p = A + (long long)arow * SS;
#pragma unroll
        for (int u = 0; u < 4; u++) areg[u] = *(const uint4*)(p + u * 8);
#pragma unroll
        for (int it = 0; it < 4; it++) {
            const int r = brow0 + it * 32;
            cpa16(sb + MATB + r * PITCH + bu * 16, Bv + (long long)r * SS + bu * 8);
        }
        cpa_commit();
    }

    float acc[4][8][4];
#pragma unroll
    for (int i = 0; i < 4; i++)
#pragma unroll
        for (int j = 0; j < 8; j++)
#pragma unroll
            for (int q = 0; q < 4; q++) acc[i][j][q] = 0.0f;

    const int NC = SS >> 5;

    for (int kc = 0; kc < NC; kc++) {
        const int s = kc & 1;
        {
            char* d = smem + s * PV_STAGEB + arow * PITCH;
#pragma unroll
            for (int u = 0; u < 4; u++) {
                const __half2* h2 = (const __half2*)&areg[u];
                __half2 o[4];
#pragma unroll
                for (int j = 0; j < 4; j++) {
                    float2 f = __half22float2(h2[j]);
                    f.x = ex2(fmaf(f.x, L2E, -tm));
                    f.y = ex2(fmaf(f.y, L2E, -tm));
                    o[j] = __float22half2_rn(f);
                }
                *(uint4*)(d + u * 16) = *(uint4*)&o[0];
            }
        }
        cpa_wait<0>();
        __syncthreads();

        const uint32_t sA = sb + s * PV_STAGEB;
        const uint32_t sB = sA + MATB;
        const int lr = lane & 15;
        const int lc = (lane >> 4) * 16;

#pragma unroll
        for (int k16 = 0; k16 < 2; k16++) {
            const uint32_t kb = k16 * 32 + lc;
            uint32_t ah[4][4], bh[4][4];
#pragma unroll
            for (int i = 0; i < 4; i++)
                ldm_x4(ah[i], sA + (uint32_t)(wm0 + i * 16 + lr) * PITCH + kb);
#pragma unroll
            for (int jj = 0; jj < 4; jj++)
                ldm_x4(bh[jj], sB + (uint32_t)(wn0 + jj * 16 + lr) * PITCH + kb);

            if (k16 == 0 && kc + 1 < NC) {
                const __half* p = A + (long long)arow * SS + (kc + 1) * 32;
#pragma unroll
                for (int u = 0; u < 4; u++) areg[u] = *(const uint4*)(p + u * 8);
#pragma unroll
                for (int it = 0; it < 4; it++) {
                    const int r = brow0 + it * 32;
                    cpa16(sb + (s ^ 1) * PV_STAGEB + MATB + r * PITCH + bu * 16,
                          Bv + (long long)r * SS + (kc + 1) * 32 + bu * 8);
                }
                cpa_commit();
            }
#pragma unroll
            for (int i = 0; i < 4; i++)
#pragma unroll
                for (int j = 0; j < 8; j++) {
                    const int jj = j >> 1, sel = j & 1;
                    mma16816(acc[i][j], ah[i], bh[jj][sel], bh[jj][sel + 2]);
                }
        }
    }

    const int er = lane >> 2;
    const int ec = (lane & 3) * 2;
#pragma unroll
    for (int i = 0; i < 4; i++) {
#pragma unroll
        for (int half_m = 0; half_m < 2; half_m++) {
            const int lrow = wm0 + i * 16 + er + half_m * 8;
            const float inv = rowinv[b * SS + row0 + lrow];
#pragma unroll
            for (int j = 0; j < 8; j++) {
                const int col = col0 + wn0 + j * 8 + ec;
                float2 v;
                v.x = acc[i][j][half_m * 2 + 0] * inv;
                v.y = acc[i][j][half_m * 2 + 1] * inv;
                *(float2*)(C + (long long)lrow * DD + col) = v;
            }
        }
    }
}

__global__ void __launch_bounds__(256)
rowstats(const __half* __restrict__ S, float* __restrict__ rowm, float* __restrict__ rowinv)
{
    const long long rb = (long long)blockIdx.x * SS;
    const int t = threadIdx.x;

    const uint4 v4 = *(const uint4*)(S + rb + t * 8);
    const __half2* h2 = (const __half2*)&v4;
    float v[8];
#pragma unroll
    for (int j = 0; j < 4; j++) {
        float2 f = __half22float2(h2[j]);
        v[2*j] = f.x; v[2*j+1] = f.y;
    }
    float m = v[0];
#pragma unroll
    for (int i = 1; i < 8; i++) m = fmaxf(m, v[i]);

    __shared__ float red[8];
#pragma unroll
    for (int o = 16; o > 0; o >>= 1) m = fmaxf(m, __shfl_xor_sync(0xffffffffu, m, o));
    if ((t & 31) == 0) red[t >> 5] = m;
    __syncthreads();
    if (t < 32) {
        float mm = (t < 8) ? red[t] : -INFINITY;
#pragma unroll
        for (int o = 4; o > 0; o >>= 1) mm = fmaxf(mm, __shfl_xor_sync(0xffffffffu, mm, o));
        if (t == 0) red[0] = mm;
    }
    __syncthreads();
    m = red[0];
    __syncthreads();

    const float tm = m * L2E;
    float sum = 0.0f;
#pragma unroll
    for (int i = 0; i < 8; i++) sum += ex2(fmaf(v[i], L2E, -tm));
#pragma unroll
    for (int o = 16; o > 0; o >>= 1) sum += __shfl_xor_sync(0xffffffffu, sum, o);
    if ((t & 31) == 0) red[t >> 5] = sum;
    __syncthreads();
    if (t < 32) {
        float ss = (t < 8) ? red[t] : 0.0f;
#pragma unroll
        for (int o = 4; o > 0; o >>= 1) ss += __shfl_xor_sync(0xffffffffu, ss, o);
        if (t == 0) {
            rowm[blockIdx.x]   = m;
            rowinv[blockIdx.x] = 1.0f / ss;
        }
    }
}

__global__ void __launch_bounds__(256)
cvt_f32_f16(const float* __restrict__ s, __half* __restrict__ h, int n4)
{
    int i = blockIdx.x * 256 + threadIdx.x;
    if (i >= n4) return;
    float4 v = ((const float4*)s)[i];
    *(__half2*)(h + 4*i)     = __halves2half2(__float2half_rn(v.x), __float2half_rn(v.y));
    *(__half2*)(h + 4*i + 2) = __halves2half2(__float2half_rn(v.z), __float2half_rn(v.w));
}

__global__ void __launch_bounds__(256)
transpose_cvt(const float* __restrict__ src, __half* __restrict__ dh, __half* __restrict__ dl,
              int R, int C, long long sS, long long sD)
{
    __shared__ float t[32][33];
    const float* S = src + (long long)blockIdx.z * sS;
    __half* DH = dh + (long long)blockIdx.z * sD;
    const int c0 = blockIdx.x * 32, r0 = blockIdx.y * 32;
    const int tx = threadIdx.x, ty = threadIdx.y;
#pragma unroll
    for (int k = 0; k < 4; k++)
        t[ty + 8*k][tx] = S[(long long)(r0 + ty + 8*k) * C + c0 + tx];
    __syncthreads();
    if (dl) {
        __half* DL = dl + (long long)blockIdx.z * sD;
#pragma unroll
        for (int k = 0; k < 4; k++) {
            float f = t[tx][ty + 8*k];
            __half h = __float2half_rn(f);
            __half l = __float2half_rn(f - __half2float(h));
            long long o = (long long)(c0 + ty + 8*k) * R + r0 + tx;
            DH[o] = h; DL[o] = l;
        }
    } else {
#pragma unroll
        for (int k = 0; k < 4; k++) {
            long long o = (long long)(c0 + ty + 8*k) * R + r0 + tx;
            DH[o] = __float2half_rn(t[tx][ty + 8*k]);
        }
    }
}

extern "C" void kernel_launch(void* const* d_in, const int* in_sizes, int n_in,
                              void* d_out, int out_size)
{
    (void)in_sizes; (void)n_in; (void)out_size;
    const float* x  = (const float*)d_in[0];
    const float* Wq = (const float*)d_in[1];
    const float* bq = (const float*)d_in[2];
    const float* Wk = (const float*)d_in[3];
    const float* bk = (const float*)d_in[4];
    const float* Wv = (const float*)d_in[5];
    const float* bv = (const float*)d_in[6];
    float* out = (float*)d_out;

    __half *xh, *Wth, *Wtl, *Qh, *Kh, *Vth, *Sc;
    float *Vf, *rowm, *rowinv;
    cudaGetSymbolAddress((void**)&xh,   g_xh);
    cudaGetSymbolAddress((void**)&Wth,  g_Wth);  cudaGetSymbolAddress((void**)&Wtl, g_Wtl);
    cudaGetSymbolAddress((void**)&Qh,   g_Qh);
    cudaGetSymbolAddress((void**)&Kh,   g_Kh);
    cudaGetSymbolAddress((void**)&Vf,   g_Vf);
    cudaGetSymbolAddress((void**)&Vth,  g_Vth);
    cudaGetSymbolAddress((void**)&Sc,   g_Sc);
    cudaGetSymbolAddress((void**)&rowm, g_rowm); cudaGetSymbolAddress((void**)&rowinv, g_rowinv);

    const int SMEM_P  = 2 * 3 * MATB;
    const int SMEM_1  = 2 * 2 * MATB;
    const int SMEM_PV = 2 * PV_STAGEB;
    cudaFuncSetAttribute((const void*)gemm_mma<1,0>, cudaFuncAttributeMaxDynamicSharedMemorySize, SMEM_P);
    cudaFuncSetAttribute((const void*)gemm_mma<1,2>, cudaFuncAttributeMaxDynamicSharedMemorySize, SMEM_P);
    cudaFuncSetAttribute((const void*)gemm_mma<0,3>, cudaFuncAttributeMaxDynamicSharedMemorySize, SMEM_1);
    cudaFuncSetAttribute((const void*)gemm_pv,       cudaFuncAttributeMaxDynamicSharedMemorySize, SMEM_PV);

    const float scale = 1.0f / sqrtf((float)DD);

    {
        dim3 tb(32, 8), tg(DD/32, DD/32, 1);
        transpose_cvt<<<tg, tb>>>(Wq, Wth + 0*DD*DD, Wtl + 0*DD*DD, DD, DD, 0, 0);
        transpose_cvt<<<tg, tb>>>(Wk, Wth + 1*DD*DD, Wtl + 1*DD*DD, DD, DD, 0, 0);
        transpose_cvt<<<tg, tb>>>(Wv, Wth + 2*DD*DD, Wtl + 2*DD*DD, DD, DD, 0, 0);
    }
    {
        int n4 = MTOT * DD / 4;
        cvt_f32_f16<<<(n4 + 255) / 256, 256>>>(x, xh, n4);
    }
    {
        dim3 g(DD/128, MTOT/128, 1);
        gemm_mma<1,2><<<g, 128, SMEM_P>>>(xh, Wth + 0*DD*DD, Wtl + 0*DD*DD, bq,
                                          nullptr, Qh, DD, DD, 1.0f, 0, 0, 0);
        gemm_mma<1,2><<<g, 128, SMEM_P>>>(xh, Wth + 1*DD*DD, Wtl + 1*DD*DD, bk,
                                          nullptr, Kh, DD, DD, 1.0f, 0, 0, 0);
        gemm_mma<1,0><<<g, 128, SMEM_P>>>(xh, Wth + 2*DD*DD, Wtl + 2*DD*DD, bv,
                                          Vf, nullptr, DD, DD, 1.0f, 0, 0, 0);
    }
    {
        dim3 g(SS/128, SS/128, BB);
        gemm_mma<0,3><<<g, 128, SMEM_1>>>(Qh, Kh, nullptr, nullptr,
                                          nullptr, Sc, SS, DD, scale,
                                          (long long)SS*DD, (long long)SS*DD,
                                          (long long)SS*SS);
    }
    {
        dim3 tb(32, 8), tg(DD/32, SS/32, BB);
        transpose_cvt<<<tg, tb>>>(Vf, Vth, nullptr, SS, DD,
                                  (long long)SS*DD, (long long)DD*SS);
    }
    rowstats<<<MTOT, 256>>>(Sc, rowm, rowinv);
    {
        dim3 g(DD/128, SS/128, BB);
        gemm_pv<<<g, 128, SMEM_PV>>>(Sc, rowm, rowinv, Vth, out);
    }
}

// round 11
// speedup vs baseline: 1.0488x; 1.0488x over previous
#include <cuda_runtime.h>
#include <cuda_fp16.h>
#include <math.h>
#include <stdint.h>

#define BB 8
#define SS 2048
#define DD 512
#define MTOT (BB*SS)

__device__ __half g_xh[MTOT*DD];
__device__ __half g_Wth[3][DD*DD], g_Wtl[3][DD*DD];
__device__ __half g_Qh[MTOT*DD];
__device__ __half g_Kh[MTOT*DD];
__device__ __half g_Vh[MTOT*DD];
__device__ __half g_Vth[MTOT*DD];
__device__ __half g_Sc[(long long)BB*SS*SS];
__device__ float  g_rowsum[MTOT];

__device__ __forceinline__ uint32_t smem_u32(const void* p){
    uint32_t a;
    asm("{ .reg .u64 t; cvta.to.shared.u64 t, %1; cvt.u32.u64 %0, t; }" : "=r"(a) : "l"(p));
    return a;
}
__device__ __forceinline__ void cpa16(uint32_t dst, const void* src){
    asm volatile("cp.async.cg.shared.global [%0], [%1], 16;" :: "r"(dst), "l"(src));
}
__device__ __forceinline__ void cpa_commit(){ asm volatile("cp.async.commit_group;"); }
template<int N> __device__ __forceinline__ void cpa_wait(){
    asm volatile("cp.async.wait_group %0;" :: "n"(N));
}
__device__ __forceinline__ void ldm_x4(uint32_t* r, uint32_t addr){
    asm volatile("ldmatrix.sync.aligned.m8n8.x4.shared.b16 {%0,%1,%2,%3}, [%4];"
        : "=r"(r[0]), "=r"(r[1]), "=r"(r[2]), "=r"(r[3]) : "r"(addr));
}
__device__ __forceinline__ void mma16816(float* d, const uint32_t* a, uint32_t b0, uint32_t b1){
    asm volatile("mma.sync.aligned.m16n8k16.row.col.f32.f16.f16.f32 "
        "{%0,%1,%2,%3},{%4,%5,%6,%7},{%8,%9},{%0,%1,%2,%3};"
        : "+f"(d[0]), "+f"(d[1]), "+f"(d[2]), "+f"(d[3])
        : "r"(a[0]), "r"(a[1]), "r"(a[2]), "r"(a[3]), "r"(b0), "r"(b1));
}
__device__ __forceinline__ float ex2(float x){
    float r;
    asm("ex2.approx.ftz.f32 %0, %1;" : "=f"(r) : "f"(x));
    return r;
}
#define L2E 1.44269504f

#define PITCH   80
#define MATB    (128*PITCH)

// 256 threads, 8 warps of 64x32, CTA tile 128x128, 2-stage cp.async, single sync.
// BSPLIT=1: C = A*(Bh+Bl)^T   BSPLIT=0: C = A*Bh^T
// EPI 2: Ch = fp16(D + bias)
// EPI 4: Ch = fp16(alpha*D), plus per-row sum of exp(Ch) atomicAdd'ed to rowsum
template<int BSPLIT, int EPI>
__global__ void __launch_bounds__(256, 2)
gemm_mma(const __half* __restrict__ Ah,
         const __half* __restrict__ Bh, const __half* __restrict__ Bl,
         const float* __restrict__ bias,
         __half* __restrict__ Ch, float* __restrict__ rowsum,
         int N, int K, float alpha,
         long long sA, long long sB, long long sC)
{
    constexpr int NMAT = 2 + BSPLIT;
    constexpr uint32_t STAGEB = NMAT * MATB;

    extern __shared__ char smem[];
    const uint32_t sb = smem_u32(smem);
    const int tid = threadIdx.x;
    const int wid = tid >> 5, lane = tid & 31;
    const int wr = wid >> 2, wc = wid & 3;
    const int wm0 = wr * 64, wn0 = wc * 32;

    const int row0 = blockIdx.y << 7, col0 = blockIdx.x << 7;
    const long long zA = (long long)blockIdx.z * sA;
    const long long zB = (long long)blockIdx.z * sB;
    const long long zC = (long long)blockIdx.z * sC;

    const __half* gsrc[NMAT];
    gsrc[0] = Ah + zA + (long long)row0 * K;
    gsrc[1] = Bh + zB + (long long)col0 * K;
    if (BSPLIT) gsrc[2] = Bl + zB + (long long)col0 * K;

    const int lrow0 = tid >> 2;
    const int lu    = tid & 3;

    float acc[4][4][4];
#pragma unroll
    for (int i = 0; i < 4; i++)
#pragma unroll
        for (int j = 0; j < 4; j++)
#pragma unroll
            for (int q = 0; q < 4; q++) acc[i][j][q] = 0.0f;

    const int NC = K >> 5;

    auto load_chunk = [&](int stage, int kc) {
        const uint32_t sdst = sb + stage * STAGEB;
#pragma unroll
        for (int m = 0; m < NMAT; m++) {
            const __half* g = gsrc[m] + kc * 32;
#pragma unroll
            for (int it = 0; it < 2; it++) {
                const int row = lrow0 + it * 64;
                cpa16(sdst + m * MATB + row * PITCH + lu * 16,
                      g + (long long)row * K + lu * 8);
            }
        }
    };

    load_chunk(0, 0);
    cpa_commit();

    for (int kc = 0; kc < NC; kc++) {
        const int s = kc & 1;
        cpa_wait<0>();
        __syncthreads();

        const uint32_t sAh = sb + s * STAGEB;
        const uint32_t sBh = sAh + MATB;
        const uint32_t sBl = sAh + 2 * MATB;
        const int lr = lane & 15;
        const int lc = (lane >> 4) * 16;

#pragma unroll
        for (int k16 = 0; k16 < 2; k16++) {
            const uint32_t kb = k16 * 32 + lc;
            uint32_t ah[4][4], bh[2][4], bl[2][4];
#pragma unroll
            for (int i = 0; i < 4; i++)
                ldm_x4(ah[i], sAh + (uint32_t)(wm0 + i * 16 + lr) * PITCH + kb);
#pragma unroll
            for (int jj = 0; jj < 2; jj++) {
                ldm_x4(bh[jj], sBh + (uint32_t)(wn0 + jj * 16 + lr) * PITCH + kb);
                if (BSPLIT) ldm_x4(bl[jj], sBl + (uint32_t)(wn0 + jj * 16 + lr) * PITCH + kb);
            }
            if (k16 == 0 && kc + 1 < NC) {
                load_chunk(s ^ 1, kc + 1);
                cpa_commit();
            }
#pragma unroll
            for (int i = 0; i < 4; i++) {
#pragma unroll
                for (int j = 0; j < 4; j++) {
                    const int jj = j >> 1, sel = j & 1;
                    mma16816(acc[i][j], ah[i], bh[jj][sel], bh[jj][sel + 2]);
                    if (BSPLIT)
                        mma16816(acc[i][j], ah[i], bl[jj][sel], bl[jj][sel + 2]);
                }
            }
        }
    }

    const int er = lane >> 2;
    const int ec = (lane & 3) * 2;
    float esum[4][2];
#pragma unroll
    for (int i = 0; i < 4; i++) { esum[i][0] = 0.0f; esum[i][1] = 0.0f; }

#pragma unroll
    for (int i = 0; i < 4; i++) {
#pragma unroll
        for (int j = 0; j < 4; j++) {
            const int col = col0 + wn0 + j * 8 + ec;
#pragma unroll
            for (int half_m = 0; half_m < 2; half_m++) {
                const int row = row0 + wm0 + i * 16 + er + half_m * 8;
                const float d0 = acc[i][j][half_m * 2 + 0];
                const float d1 = acc[i][j][half_m * 2 + 1];
                if (EPI == 2) {
                    float f0 = d0 + bias[col];
                    float f1 = d1 + bias[col + 1];
                    *(__half2*)(Ch + zC + (long long)row * N + col) =
                        __halves2half2(__float2half_rn(f0), __float2half_rn(f1));
                } else {
                    __half h0 = __float2half_rn(d0 * alpha);
                    __half h1 = __float2half_rn(d1 * alpha);
                    *(__half2*)(Ch + zC + (long long)row * N + col) = __halves2half2(h0, h1);
                    esum[i][half_m] += ex2(__half2float(h0) * L2E) + ex2(__half2float(h1) * L2E);
                }
            }
        }
    }

    if (EPI == 4) {
        __syncthreads();                 // stage buffers dead; reuse smem
        float* red = (float*)smem;       // [128][4]
#pragma unroll
        for (int i = 0; i < 4; i++) {
#pragma unroll
            for (int half_m = 0; half_m < 2; half_m++) {
                float s = esum[i][half_m];
                s += __shfl_xor_sync(0xffffffffu, s, 1);
                s += __shfl_xor_sync(0xffffffffu, s, 2);
                if ((lane & 3) == 0)
                    red[(wm0 + i * 16 + half_m * 8 + er) * 4 + wc] = s;
            }
        }
        __syncthreads();
        if (tid < 128) {
            float s = red[tid*4+0] + red[tid*4+1] + red[tid*4+2] + red[tid*4+3];
            atomicAdd(&rowsum[(long long)blockIdx.z * SS + row0 + tid], s);
        }
    }
}

// fused softmax+PV: out = (exp(S) @ V^T) / rowsum, 256 thr, 8 warps of 64x32
#define PV_STAGEB (2*MATB)
__global__ void __launch_bounds__(256, 2)
gemm_pv(const __half* __restrict__ Sc, const float* __restrict__ rowsum,
        const __half* __restrict__ Vt, float* __restrict__ out)
{
    extern __shared__ char smem[];
    const uint32_t sb = smem_u32(smem);
    const int tid = threadIdx.x;
    const int wid = tid >> 5, lane = tid & 31;
    const int wr = wid >> 2, wc = wid & 3;
    const int wm0 = wr * 64, wn0 = wc * 32;

    const int col0 = blockIdx.x << 7, row0 = blockIdx.y << 7, b = blockIdx.z;
    const __half* A  = Sc + ((long long)(b * SS + row0)) * SS;
    const __half* Bv = Vt + ((long long)(b * DD + col0)) * SS;
    float* C = out + ((long long)(b * SS + row0)) * DD;

    const int arow  = tid >> 1;
    const int acolh = (tid & 1) * 16;
    const int brow0 = tid >> 2, bu = tid & 3;

    uint4 areg0, areg1;
    {
        const __half* p = A + (long long)arow * SS + acolh;
        areg0 = *(const uint4*)p;
        areg1 = *(const uint4*)(p + 8);
#pragma unroll
        for (int it = 0; it < 2; it++) {
            const int r = brow0 + it * 64;
            cpa16(sb + MATB + r * PITCH + bu * 16, Bv + (long long)r * SS + bu * 8);
        }
        cpa_commit();
    }

    float acc[4][4][4];
#pragma unroll
    for (int i = 0; i < 4; i++)
#pragma unroll
        for (int j = 0; j < 4; j++)
#pragma unroll
            for (int q = 0; q < 4; q++) acc[i][j][q] = 0.0f;

    const int NC = SS >> 5;

    for (int kc = 0; kc < NC; kc++) {
        const int s = kc & 1;
        {
            char* d = smem + s * PV_STAGEB + arow * PITCH + acolh * 2;
            __half2 o[8];
            const __half2* h2a = (const __half2*)&areg0;
            const __half2* h2b = (const __half2*)&areg1;
#pragma unroll
            for (int j = 0; j < 4; j++) {
                float2 f = __half22float2(h2a[j]);
                f.x = ex2(f.x * L2E);
                f.y = ex2(f.y * L2E);
                o[j] = __float22half2_rn(f);
            }
#pragma unroll
            for (int j = 0; j < 4; j++) {
                float2 f = __half22float2(h2b[j]);
                f.x = ex2(f.x * L2E);
                f.y = ex2(f.y * L2E);
                o[4 + j] = __float22half2_rn(f);
            }
            *(uint4*)d        = *(uint4*)&o[0];
            *(uint4*)(d + 16) = *(uint4*)&o[4];
        }
        cpa_wait<0>();
        __syncthreads();

        const uint32_t sA = sb + s * PV_STAGEB;
        const uint32_t sB = sA + MATB;
        const int lr = lane & 15;
        const int lc = (lane >> 4) * 16;

#pragma unroll
        for (int k16 = 0; k16 < 2; k16++) {
            const uint32_t kb = k16 * 32 + lc;
            uint32_t ah[4][4], bh[2][4];
#pragma unroll
            for (int i = 0; i < 4; i++)
                ldm_x4(ah[i], sA + (uint32_t)(wm0 + i * 16 + lr) * PITCH + kb);
#pragma unroll
            for (int jj = 0; jj < 2; jj++)
                ldm_x4(bh[jj], sB + (uint32_t)(wn0 + jj * 16 + lr) * PITCH + kb);

            if (k16 == 0 && kc + 1 < NC) {
                const __half* p = A + (long long)arow * SS + (kc + 1) * 32 + acolh;
                areg0 = *(const uint4*)p;
                areg1 = *(const uint4*)(p + 8);
#pragma unroll
                for (int it = 0; it < 2; it++) {
                    const int r = brow0 + it * 64;
                    cpa16(sb + (s ^ 1) * PV_STAGEB + MATB + r * PITCH + bu * 16,
                          Bv + (long long)r * SS + (kc + 1) * 32 + bu * 8);
                }
                cpa_commit();
            }
#pragma unroll
            for (int i = 0; i < 4; i++)
#pragma unroll
                for (int j = 0; j < 4; j++) {
                    const int jj = j >> 1, sel = j & 1;
                    mma16816(acc[i][j], ah[i], bh[jj][sel], bh[jj][sel + 2]);
                }
        }
    }

    const int er = lane >> 2;
    const int ec = (lane & 3) * 2;
#pragma unroll
    for (int i = 0; i < 4; i++) {
#pragma unroll
        for (int half_m = 0; half_m < 2; half_m++) {
            const int lrow = wm0 + i * 16 + er + half_m * 8;
            const float inv = 1.0f / rowsum[b * SS + row0 + lrow];
#pragma unroll
            for (int j = 0; j < 4; j++) {
                const int col = col0 + wn0 + j * 8 + ec;
                float2 v;
                v.x = acc[i][j][half_m * 2 + 0] * inv;
                v.y = acc[i][j][half_m * 2 + 1] * inv;
                *(float2*)(C + (long long)lrow * DD + col) = v;
            }
        }
    }
}

__global__ void __launch_bounds__(256)
cvt_f32_f16(const float* __restrict__ s, __half* __restrict__ h, int n4)
{
    int i = blockIdx.x * 256 + threadIdx.x;
    if (i >= n4) return;
    float4 v = ((const float4*)s)[i];
    *(__half2*)(h + 4*i)     = __halves2half2(__float2half_rn(v.x), __float2half_rn(v.y));
    *(__half2*)(h + 4*i + 2) = __halves2half2(__float2half_rn(v.z), __float2half_rn(v.w));
}

// fp32 [R,C] -> fp16 hi/lo [C,R]
__global__ void __launch_bounds__(256)
transpose_split(const float* __restrict__ src, __half* __restrict__ dh, __half* __restrict__ dl,
                int R, int C)
{
    __shared__ float t[32][33];
    const int c0 = blockIdx.x * 32, r0 = blockIdx.y * 32;
    const int tx = threadIdx.x, ty = threadIdx.y;
#pragma unroll
    for (int k = 0; k < 4; k++)
        t[ty + 8*k][tx] = src[(long long)(r0 + ty + 8*k) * C + c0 + tx];
    __syncthreads();
#pragma unroll
    for (int k = 0; k < 4; k++) {
        float f = t[tx][ty + 8*k];
        __half h = __float2half_rn(f);
        __half l = __float2half_rn(f - __half2float(h));
        long long o = (long long)(c0 + ty + 8*k) * R + r0 + tx;
        dh[o] = h; dl[o] = l;
    }
}

// fp16 [R,C] -> fp16 [C,R] per batch
__global__ void __launch_bounds__(256)
transpose_h16(const __half* __restrict__ src, __half* __restrict__ dst,
              int R, int C, long long sS, long long sD)
{
    __shared__ __half t[32][34];
    const __half* S = src + (long long)blockIdx.z * sS;
    __half* D = dst + (long long)blockIdx.z * sD;
    const int c0 = blockIdx.x * 32, r0 = blockIdx.y * 32;
    const int tx = threadIdx.x, ty = threadIdx.y;
#pragma unroll
    for (int k = 0; k < 4; k++)
        t[ty + 8*k][tx] = S[(long long)(r0 + ty + 8*k) * C + c0 + tx];
    __syncthreads();
#pragma unroll
    for (int k = 0; k < 4; k++)
        D[(long long)(c0 + ty + 8*k) * R + r0 + tx] = t[tx][ty + 8*k];
}

extern "C" void kernel_launch(void* const* d_in, const int* in_sizes, int n_in,
                              void* d_out, int out_size)
{
    (void)in_sizes; (void)n_in; (void)out_size;
    const float* x  = (const float*)d_in[0];
    const float* Wq = (const float*)d_in[1];
    const float* bq = (const float*)d_in[2];
    const float* Wk = (const float*)d_in[3];
    const float* bk = (const float*)d_in[4];
    const float* Wv = (const float*)d_in[5];
    const float* bv = (const float*)d_in[6];
    float* out = (float*)d_out;

    __half *xh, *Wth, *Wtl, *Qh, *Kh, *Vh, *Vth, *Sc;
    float *rowsum;
    cudaGetSymbolAddress((void**)&xh,     g_xh);
    cudaGetSymbolAddress((void**)&Wth,    g_Wth);  cudaGetSymbolAddress((void**)&Wtl, g_Wtl);
    cudaGetSymbolAddress((void**)&Qh,     g_Qh);
    cudaGetSymbolAddress((void**)&Kh,     g_Kh);
    cudaGetSymbolAddress((void**)&Vh,     g_Vh);
    cudaGetSymbolAddress((void**)&Vth,    g_Vth);
    cudaGetSymbolAddress((void**)&Sc,     g_Sc);
    cudaGetSymbolAddress((void**)&rowsum, g_rowsum);

    const int SMEM_P  = 2 * 3 * MATB;   // 61440
    const int SMEM_1  = 2 * 2 * MATB;   // 40960
    const int SMEM_PV = 2 * PV_STAGEB;  // 40960
    cudaFuncSetAttribute((const void*)gemm_mma<1,2>, cudaFuncAttributeMaxDynamicSharedMemorySize, SMEM_P);
    cudaFuncSetAttribute((const void*)gemm_mma<0,4>, cudaFuncAttributeMaxDynamicSharedMemorySize, SMEM_1);
    cudaFuncSetAttribute((const void*)gemm_pv,       cudaFuncAttributeMaxDynamicSharedMemorySize, SMEM_PV);

    const float scale = 1.0f / sqrtf((float)DD);

    {
        dim3 tb(32, 8), tg(DD/32, DD/32);
        transpose_split<<<tg, tb>>>(Wq, Wth + 0*DD*DD, Wtl + 0*DD*DD, DD, DD);
        transpose_split<<<tg, tb>>>(Wk, Wth + 1*DD*DD, Wtl + 1*DD*DD, DD, DD);
        transpose_split<<<tg, tb>>>(Wv, Wth + 2*DD*DD, Wtl + 2*DD*DD, DD, DD);
    }
    {
        int n4 = MTOT * DD / 4;
        cvt_f32_f16<<<(n4 + 255) / 256, 256>>>(x, xh, n4);
    }
    {
        dim3 g(DD/128, MTOT/128, 1);
        gemm_mma<1,2><<<g, 256, SMEM_P>>>(xh, Wth + 0*DD*DD, Wtl + 0*DD*DD, bq,
                                          Qh, nullptr, DD, DD, 1.0f, 0, 0, 0);
        gemm_mma<1,2><<<g, 256, SMEM_P>>>(xh, Wth + 1*DD*DD, Wtl + 1*DD*DD, bk,
                                          Kh, nullptr, DD, DD, 1.0f, 0, 0, 0);
        gemm_mma<1,2><<<g, 256, SMEM_P>>>(xh, Wth + 2*DD*DD, Wtl + 2*DD*DD, bv,
                                          Vh, nullptr, DD, DD, 1.0f, 0, 0, 0);
    }
    // V^T per batch (fp16 -> fp16)
    {
        dim3 tb(32, 8), tg(DD/32, SS/32, BB);
        transpose_h16<<<tg, tb>>>(Vh, Vth, SS, DD, (long long)SS*DD, (long long)DD*SS);
    }
    cudaMemsetAsync(rowsum, 0, MTOT * sizeof(float));
    // scores + per-row exp-sum
    {
        dim3 g(SS/128, SS/128, BB);
        gemm_mma<0,4><<<g, 256, SMEM_1>>>(Qh, Kh, nullptr, nullptr,
                                          Sc, rowsum, SS, DD, scale,
                                          (long long)SS*DD, (long long)SS*DD,
                                          (long long)SS*SS);
    }
    // fused exp + PV + normalize
    {
        dim3 g(DD/128, SS/128, BB);
        gemm_pv<<<g, 256, SMEM_PV>>>(Sc, rowsum, Vth, out);
    }
}

// round 12
// speedup vs baseline: 1.2325x; 1.1752x over previous
#include <cuda_runtime.h>
#include <cuda_fp16.h>
#include <math.h>
#include <stdint.h>

#define BB 8
#define SS 2048
#define DD 512
#define MTOT (BB*SS)

__device__ __half g_xh[MTOT*DD];
__device__ __half g_Wth[3][DD*DD];
__device__ __half g_Qh[MTOT*DD];
__device__ __half g_Kh[MTOT*DD];
__device__ __half g_Vh[MTOT*DD];
__device__ __half g_Vth[MTOT*DD];
__device__ __half g_Sc[(long long)BB*SS*SS];
__device__ float  g_rowsum[MTOT];

__device__ __forceinline__ uint32_t smem_u32(const void* p){
    uint32_t a;
    asm("{ .reg .u64 t; cvta.to.shared.u64 t, %1; cvt.u32.u64 %0, t; }" : "=r"(a) : "l"(p));
    return a;
}
__device__ __forceinline__ void cpa16(uint32_t dst, const void* src){
    asm volatile("cp.async.cg.shared.global [%0], [%1], 16;" :: "r"(dst), "l"(src));
}
__device__ __forceinline__ void cpa_commit(){ asm volatile("cp.async.commit_group;"); }
template<int N> __device__ __forceinline__ void cpa_wait(){
    asm volatile("cp.async.wait_group %0;" :: "n"(N));
}
__device__ __forceinline__ void ldm_x4(uint32_t* r, uint32_t addr){
    asm volatile("ldmatrix.sync.aligned.m8n8.x4.shared.b16 {%0,%1,%2,%3}, [%4];"
        : "=r"(r[0]), "=r"(r[1]), "=r"(r[2]), "=r"(r[3]) : "r"(addr));
}
__device__ __forceinline__ void mma16816(float* d, const uint32_t* a, uint32_t b0, uint32_t b1){
    asm volatile("mma.sync.aligned.m16n8k16.row.col.f32.f16.f16.f32 "
        "{%0,%1,%2,%3},{%4,%5,%6,%7},{%8,%9},{%0,%1,%2,%3};"
        : "+f"(d[0]), "+f"(d[1]), "+f"(d[2]), "+f"(d[3])
        : "r"(a[0]), "r"(a[1]), "r"(a[2]), "r"(a[3]), "r"(b0), "r"(b1));
}
__device__ __forceinline__ float ex2(float x){
    float r;
    asm("ex2.approx.ftz.f32 %0, %1;" : "=f"(r) : "f"(x));
    return r;
}
#define L2E 1.44269504f

#define PITCH   80
#define MATB    (128*PITCH)

// 256 threads, 8 warps of 64x32, CTA tile 128x128, 2-stage cp.async, single sync.
// 1-term plain fp16: C = A * B^T
// EPI 2: Ch = fp16(D + bias)
// EPI 4: Ch = fp16(alpha*D), plus per-row sum of exp(Ch) atomicAdd'ed to rowsum
template<int EPI>
__global__ void __launch_bounds__(256, 2)
gemm_mma(const __half* __restrict__ Ah, const __half* __restrict__ Bh,
         const float* __restrict__ bias,
         __half* __restrict__ Ch, float* __restrict__ rowsum,
         int N, int K, float alpha,
         long long sA, long long sB, long long sC)
{
    constexpr uint32_t STAGEB = 2 * MATB;

    extern __shared__ char smem[];
    const uint32_t sb = smem_u32(smem);
    const int tid = threadIdx.x;
    const int wid = tid >> 5, lane = tid & 31;
    const int wr = wid >> 2, wc = wid & 3;
    const int wm0 = wr * 64, wn0 = wc * 32;

    const int row0 = blockIdx.y << 7, col0 = blockIdx.x << 7;
    const long long zA = (long long)blockIdx.z * sA;
    const long long zB = (long long)blockIdx.z * sB;
    const long long zC = (long long)blockIdx.z * sC;

    const __half* gsrc[2] = { Ah + zA + (long long)row0 * K,
                              Bh + zB + (long long)col0 * K };

    const int lrow0 = tid >> 2;
    const int lu    = tid & 3;

    float acc[4][4][4];
#pragma unroll
    for (int i = 0; i < 4; i++)
#pragma unroll
        for (int j = 0; j < 4; j++)
#pragma unroll
            for (int q = 0; q < 4; q++) acc[i][j][q] = 0.0f;

    const int NC = K >> 5;

    auto load_chunk = [&](int stage, int kc) {
        const uint32_t sdst = sb + stage * STAGEB;
#pragma unroll
        for (int m = 0; m < 2; m++) {
            const __half* g = gsrc[m] + kc * 32;
#pragma unroll
            for (int it = 0; it < 2; it++) {
                const int row = lrow0 + it * 64;
                cpa16(sdst + m * MATB + row * PITCH + lu * 16,
                      g + (long long)row * K + lu * 8);
            }
        }
    };

    load_chunk(0, 0);
    cpa_commit();

    for (int kc = 0; kc < NC; kc++) {
        const int s = kc & 1;
        cpa_wait<0>();
        __syncthreads();

        const uint32_t sAh = sb + s * STAGEB;
        const uint32_t sBh = sAh + MATB;
        const int lr = lane & 15;
        const int lc = (lane >> 4) * 16;

#pragma unroll
        for (int k16 = 0; k16 < 2; k16++) {
            const uint32_t kb = k16 * 32 + lc;
            uint32_t ah[4][4], bh[2][4];
#pragma unroll
            for (int i = 0; i < 4; i++)
                ldm_x4(ah[i], sAh + (uint32_t)(wm0 + i * 16 + lr) * PITCH + kb);
#pragma unroll
            for (int jj = 0; jj < 2; jj++)
                ldm_x4(bh[jj], sBh + (uint32_t)(wn0 + jj * 16 + lr) * PITCH + kb);
            if (k16 == 0 && kc + 1 < NC) {
                load_chunk(s ^ 1, kc + 1);
                cpa_commit();
            }
#pragma unroll
            for (int i = 0; i < 4; i++)
#pragma unroll
                for (int j = 0; j < 4; j++) {
                    const int jj = j >> 1, sel = j & 1;
                    mma16816(acc[i][j], ah[i], bh[jj][sel], bh[jj][sel + 2]);
                }
        }
    }

    const int er = lane >> 2;
    const int ec = (lane & 3) * 2;
    float esum[4][2];
#pragma unroll
    for (int i = 0; i < 4; i++) { esum[i][0] = 0.0f; esum[i][1] = 0.0f; }

#pragma unroll
    for (int i = 0; i < 4; i++) {
#pragma unroll
        for (int j = 0; j < 4; j++) {
            const int col = col0 + wn0 + j * 8 + ec;
#pragma unroll
            for (int half_m = 0; half_m < 2; half_m++) {
                const int row = row0 + wm0 + i * 16 + er + half_m * 8;
                const float d0 = acc[i][j][half_m * 2 + 0];
                const float d1 = acc[i][j][half_m * 2 + 1];
                if (EPI == 2) {
                    float f0 = d0 + bias[col];
                    float f1 = d1 + bias[col + 1];
                    *(__half2*)(Ch + zC + (long long)row * N + col) =
                        __halves2half2(__float2half_rn(f0), __float2half_rn(f1));
                } else {
                    __half h0 = __float2half_rn(d0 * alpha);
                    __half h1 = __float2half_rn(d1 * alpha);
                    *(__half2*)(Ch + zC + (long long)row * N + col) = __halves2half2(h0, h1);
                    esum[i][half_m] += ex2(__half2float(h0) * L2E) + ex2(__half2float(h1) * L2E);
                }
            }
        }
    }

    if (EPI == 4) {
        __syncthreads();
        float* red = (float*)smem;   // [128][4]
#pragma unroll
        for (int i = 0; i < 4; i++) {
#pragma unroll
            for (int half_m = 0; half_m < 2; half_m++) {
                float s = esum[i][half_m];
                s += __shfl_xor_sync(0xffffffffu, s, 1);
                s += __shfl_xor_sync(0xffffffffu, s, 2);
                if ((lane & 3) == 0)
                    red[(wm0 + i * 16 + half_m * 8 + er) * 4 + wc] = s;
            }
        }
        __syncthreads();
        if (tid < 128) {
            float s = red[tid*4+0] + red[tid*4+1] + red[tid*4+2] + red[tid*4+3];
            atomicAdd(&rowsum[(long long)blockIdx.z * SS + row0 + tid], s);
        }
    }
}

// fused softmax+PV: out = (exp(S) @ V^T) / rowsum
#define PV_STAGEB (2*MATB)
__global__ void __launch_bounds__(256, 2)
gemm_pv(const __half* __restrict__ Sc, const float* __restrict__ rowsum,
        const __half* __restrict__ Vt, float* __restrict__ out)
{
    extern __shared__ char smem[];
    const uint32_t sb = smem_u32(smem);
    const int tid = threadIdx.x;
    const int wid = tid >> 5, lane = tid & 31;
    const int wr = wid >> 2, wc = wid & 3;
    const int wm0 = wr * 64, wn0 = wc * 32;

    const int col0 = blockIdx.x << 7, row0 = blockIdx.y << 7, b = blockIdx.z;
    const __half* A  = Sc + ((long long)(b * SS + row0)) * SS;
    const __half* Bv = Vt + ((long long)(b * DD + col0)) * SS;
    float* C = out + ((long long)(b * SS + row0)) * DD;

    const int arow  = tid >> 1;
    const int acolh = (tid & 1) * 16;
    const int brow0 = tid >> 2, bu = tid & 3;

    uint4 areg0, areg1;
    {
        const __half* p = A + (long long)arow * SS + acolh;
        areg0 = *(const uint4*)p;
        areg1 = *(const uint4*)(p + 8);
#pragma unroll
        for (int it = 0; it < 2; it++) {
            const int r = brow0 + it * 64;
            cpa16(sb + MATB + r * PITCH + bu * 16, Bv + (long long)r * SS + bu * 8);
        }
        cpa_commit();
    }

    float acc[4][4][4];
#pragma unroll
    for (int i = 0; i < 4; i++)
#pragma unroll
        for (int j = 0; j < 4; j++)
#pragma unroll
            for (int q = 0; q < 4; q++) acc[i][j][q] = 0.0f;

    const int NC = SS >> 5;

    for (int kc = 0; kc < NC; kc++) {
        const int s = kc & 1;
        {
            char* d = smem + s * PV_STAGEB + arow * PITCH + acolh * 2;
            __half2 o[8];
            const __half2* h2a = (const __half2*)&areg0;
            const __half2* h2b = (const __half2*)&areg1;
#pragma unroll
            for (int j = 0; j < 4; j++) {
                float2 f = __half22float2(h2a[j]);
                f.x = ex2(f.x * L2E);
                f.y = ex2(f.y * L2E);
                o[j] = __float22half2_rn(f);
            }
#pragma unroll
            for (int j = 0; j < 4; j++) {
                float2 f = __half22float2(h2b[j]);
                f.x = ex2(f.x * L2E);
                f.y = ex2(f.y * L2E);
                o[4 + j] = __float22half2_rn(f);
            }
            *(uint4*)d        = *(uint4*)&o[0];
            *(uint4*)(d + 16) = *(uint4*)&o[4];
        }
        cpa_wait<0>();
        __syncthreads();

        const uint32_t sA = sb + s * PV_STAGEB;
        const uint32_t sB = sA + MATB;
        const int lr = lane & 15;
        const int lc = (lane >> 4) * 16;

#pragma unroll
        for (int k16 = 0; k16 < 2; k16++) {
            const uint32_t kb = k16 * 32 + lc;
            uint32_t ah[4][4], bh[2][4];
#pragma unroll
            for (int i = 0; i < 4; i++)
                ldm_x4(ah[i], sA + (uint32_t)(wm0 + i * 16 + lr) * PITCH + kb);
#pragma unroll
            for (int jj = 0; jj < 2; jj++)
                ldm_x4(bh[jj], sB + (uint32_t)(wn0 + jj * 16 + lr) * PITCH + kb);

            if (k16 == 0 && kc + 1 < NC) {
                const __half* p = A + (long long)arow * SS + (kc + 1) * 32 + acolh;
                areg0 = *(const uint4*)p;
                areg1 = *(const uint4*)(p + 8);
#pragma unroll
                for (int it = 0; it < 2; it++) {
                    const int r = brow0 + it * 64;
                    cpa16(sb + (s ^ 1) * PV_STAGEB + MATB + r * PITCH + bu * 16,
                          Bv + (long long)r * SS + (kc + 1) * 32 + bu * 8);
                }
                cpa_commit();
            }
#pragma unroll
            for (int i = 0; i < 4; i++)
#pragma unroll
                for (int j = 0; j < 4; j++) {
                    const int jj = j >> 1, sel = j & 1;
                    mma16816(acc[i][j], ah[i], bh[jj][sel], bh[jj][sel + 2]);
                }
        }
    }

    const int er = lane >> 2;
    const int ec = (lane & 3) * 2;
#pragma unroll
    for (int i = 0; i < 4; i++) {
#pragma unroll
        for (int half_m = 0; half_m < 2; half_m++) {
            const int lrow = wm0 + i * 16 + er + half_m * 8;
            const float inv = 1.0f / rowsum[b * SS + row0 + lrow];
#pragma unroll
            for (int j = 0; j < 4; j++) {
                const int col = col0 + wn0 + j * 8 + ec;
                float2 v;
                v.x = acc[i][j][half_m * 2 + 0] * inv;
                v.y = acc[i][j][half_m * 2 + 1] * inv;
                *(float2*)(C + (long long)lrow * DD + col) = v;
            }
        }
    }
}

__global__ void __launch_bounds__(256)
cvt_f32_f16(const float* __restrict__ s, __half* __restrict__ h, int n4)
{
    int i = blockIdx.x * 256 + threadIdx.x;
    if (i >= n4) return;
    float4 v = ((const float4*)s)[i];
    *(__half2*)(h + 4*i)     = __halves2half2(__float2half_rn(v.x), __float2half_rn(v.y));
    *(__half2*)(h + 4*i + 2) = __halves2half2(__float2half_rn(v.z), __float2half_rn(v.w));
}

// fp32 [R,C] -> fp16 [C,R]
__global__ void __launch_bounds__(256)
transpose_cvt(const float* __restrict__ src, __half* __restrict__ dst, int R, int C)
{
    __shared__ float t[32][33];
    const int c0 = blockIdx.x * 32, r0 = blockIdx.y * 32;
    const int tx = threadIdx.x, ty = threadIdx.y;
#pragma unroll
    for (int k = 0; k < 4; k++)
        t[ty + 8*k][tx] = src[(long long)(r0 + ty + 8*k) * C + c0 + tx];
    __syncthreads();
#pragma unroll
    for (int k = 0; k < 4; k++)
        dst[(long long)(c0 + ty + 8*k) * R + r0 + tx] = __float2half_rn(t[tx][ty + 8*k]);
}

// fp16 [R,C] -> fp16 [C,R] per batch
__global__ void __launch_bounds__(256)
transpose_h16(const __half* __restrict__ src, __half* __restrict__ dst,
              int R, int C, long long sS, long long sD)
{
    __shared__ __half t[32][34];
    const __half* S = src + (long long)blockIdx.z * sS;
    __half* D = dst + (long long)blockIdx.z * sD;
    const int c0 = blockIdx.x * 32, r0 = blockIdx.y * 32;
    const int tx = threadIdx.x, ty = threadIdx.y;
#pragma unroll
    for (int k = 0; k < 4; k++)
        t[ty + 8*k][tx] = S[(long long)(r0 + ty + 8*k) * C + c0 + tx];
    __syncthreads();
#pragma unroll
    for (int k = 0; k < 4; k++)
        D[(long long)(c0 + ty + 8*k) * R + r0 + tx] = t[tx][ty + 8*k];
}

extern "C" void kernel_launch(void* const* d_in, const int* in_sizes, int n_in,
                              void* d_out, int out_size)
{
    (void)in_sizes; (void)n_in; (void)out_size;
    const float* x  = (const float*)d_in[0];
    const float* Wq = (const float*)d_in[1];
    const float* bq = (const float*)d_in[2];
    const float* Wk = (const float*)d_in[3];
    const float* bk = (const float*)d_in[4];
    const float* Wv = (const float*)d_in[5];
    const float* bv = (const float*)d_in[6];
    float* out = (float*)d_out;

    __half *xh, *Wth, *Qh, *Kh, *Vh, *Vth, *Sc;
    float *rowsum;
    cudaGetSymbolAddress((void**)&xh,     g_xh);
    cudaGetSymbolAddress((void**)&Wth,    g_Wth);
    cudaGetSymbolAddress((void**)&Qh,     g_Qh);
    cudaGetSymbolAddress((void**)&Kh,     g_Kh);
    cudaGetSymbolAddress((void**)&Vh,     g_Vh);
    cudaGetSymbolAddress((void**)&Vth,    g_Vth);
    cudaGetSymbolAddress((void**)&Sc,     g_Sc);
    cudaGetSymbolAddress((void**)&rowsum, g_rowsum);

    const int SMEM_G  = 2 * 2 * MATB;   // 40960
    cudaFuncSetAttribute((const void*)gemm_mma<2>, cudaFuncAttributeMaxDynamicSharedMemorySize, SMEM_G);
    cudaFuncSetAttribute((const void*)gemm_mma<4>, cudaFuncAttributeMaxDynamicSharedMemorySize, SMEM_G);
    cudaFuncSetAttribute((const void*)gemm_pv,     cudaFuncAttributeMaxDynamicSharedMemorySize, SMEM_G);

    const float scale = 1.0f / sqrtf((float)DD);

    {
        dim3 tb(32, 8), tg(DD/32, DD/32);
        transpose_cvt<<<tg, tb>>>(Wq, Wth + 0*DD*DD, DD, DD);
        transpose_cvt<<<tg, tb>>>(Wk, Wth + 1*DD*DD, DD, DD);
        transpose_cvt<<<tg, tb>>>(Wv, Wth + 2*DD*DD, DD, DD);
    }
    {
        int n4 = MTOT * DD / 4;
        cvt_f32_f16<<<(n4 + 255) / 256, 256>>>(x, xh, n4);
    }
    {
        dim3 g(DD/128, MTOT/128, 1);
        gemm_mma<2><<<g, 256, SMEM_G>>>(xh, Wth + 0*DD*DD, bq, Qh, nullptr,
                                        DD, DD, 1.0f, 0, 0, 0);
        gemm_mma<2><<<g, 256, SMEM_G>>>(xh, Wth + 1*DD*DD, bk, Kh, nullptr,
                                        DD, DD, 1.0f, 0, 0, 0);
        gemm_mma<2><<<g, 256, SMEM_G>>>(xh, Wth + 2*DD*DD, bv, Vh, nullptr,
                                        DD, DD, 1.0f, 0, 0, 0);
    }
    {
        dim3 tb(32, 8), tg(DD/32, SS/32, BB);
        transpose_h16<<<tg, tb>>>(Vh, Vth, SS, DD, (long long)SS*DD, (long long)DD*SS);
    }
    cudaMemsetAsync(rowsum, 0, MTOT * sizeof(float));
    {
        dim3 g(SS/128, SS/128, BB);
        gemm_mma<4><<<g, 256, SMEM_G>>>(Qh, Kh, nullptr, Sc, rowsum,
                                        SS, DD, scale,
                                        (long long)SS*DD, (long long)SS*DD,
                                        (long long)SS*SS);
    }
    {
        dim3 g(DD/128, SS/128, BB);
        gemm_pv<<<g, 256, SMEM_G>>>(Sc, rowsum, Vth, out);
    }
}